// round 5
// baseline (speedup 1.0000x reference)
#include <cuda_runtime.h>
#include <cuda_bf16.h>
#include <math.h>

#define BATCH 32
#define HW    512
#define NPIX  (HW*HW)            // 262144
#define WPR   16                 // 32-bit words per row
#define G4PB  (NPIX/4)           // 65536 float4 groups per batch
#define NTHR  254

#define ROWS  16                 // rows per strip
#define NSTR  (HW/ROWS)          // 32 strips
#define HALO  (ROWS+4)           // 20
#define NLW   (HALO*WPR)         // 320 halo words
#define SW    (ROWS*WPR)         // 256 strip words (== blockDim)
#define CAP   (SW*8)             // 2048 max worklist entries per strip
#define NBLK  (NSTR*BATCH)       // 1024

// ---------------- device scratch (overwrite-style; counters self-reset via wrap) ----------------
__device__ unsigned g_wl[BATCH][NSTR][CAP];      // worklist segments
__device__ unsigned g_wln[BATCH][NSTR];
__device__ unsigned g_histp[BATCH][NSTR][256];   // per-strip hist partials
__device__ unsigned g_cntp[BATCH][NSTR];
__device__ float    g_sqp[BATCH][NSTR];
__device__ float    g_t1[BATCH];
__device__ float    g_t2[BATCH];
__device__ unsigned g_done1[BATCH];              // wraps 0..NSTR-1
__device__ unsigned g_done2;                     // wraps 0..NBLK-1

// ======== K1: pack + dilate + worklist + histogram + (last block per batch) Otsu ========
__global__ __launch_bounds__(256) void fusedKernel(const float* __restrict__ labels,
                                                   const float* __restrict__ images) {
    const int b = blockIdx.y, strip = blockIdx.x;
    const int row0 = strip * ROWS;
    const int tid = threadIdx.x, lane = tid & 31, warp = tid >> 5;

    __shared__ unsigned lw[NLW];
    __shared__ unsigned hwv[NLW];
    __shared__ unsigned stage[CAP];
    __shared__ unsigned sh_hist[256];
    __shared__ unsigned s_n;
    __shared__ unsigned wcnt[8];
    __shared__ unsigned s_rank;

    sh_hist[tid] = 0u;
    if (tid == 0) s_n = 0u;
    for (int w = tid; w < NLW; w += 256) lw[w] = 0u;
    __syncthreads();

    // ---- phase A: pack label bits (float4 stream, streaming hint) ----
    const float4* lab4 = (const float4*)labels + (size_t)b * G4PB;
    for (int q = tid; q < HALO * 128; q += 256) {
        int r = q >> 7, c4 = q & 127;
        int grow = row0 - 2 + r;
        if (grow >= 0 && grow < HW) {
            float4 v = __ldcs(lab4 + grow * 128 + c4);
            unsigned nib = (unsigned)(v.x > 0.0f) | ((unsigned)(v.y > 0.0f) << 1)
                         | ((unsigned)(v.z > 0.0f) << 2) | ((unsigned)(v.w > 0.0f) << 3);
            if (nib) atomicOr(&lw[r * WPR + (c4 >> 3)], nib << ((c4 & 7) * 4));
        }
    }
    __syncthreads();

    // ---- phase B: horizontal dilation radius 2 ----
    for (int w = tid; w < NLW; w += 256) {
        int wc = w & 15;
        unsigned C = lw[w];
        unsigned L = wc ? lw[w - 1] : 0u;
        unsigned R = (wc < 15) ? lw[w + 1] : 0u;
        hwv[w] = C | (C << 1) | (C << 2) | (C >> 1) | (C >> 2)
               | (L >> 31) | (L >> 30) | (R << 31) | (R << 30);
    }
    __syncthreads();

    // ---- phase C: vertical OR + count + warp-aggregated worklist staging ----
    // SW == blockDim: each thread owns exactly one mask word
    {
        int w = tid;
        int r = w >> 4, wc = w & 15;
        unsigned m = hwv[w] | hwv[w + 16] | hwv[w + 32] | hwv[w + 48] | hwv[w + 64];
        unsigned cnt = __popc(m);

        unsigned nz = 0;
        #pragma unroll
        for (int k = 0; k < 8; k++) if ((m >> (k * 4)) & 0xFu) nz |= 1u << k;
        unsigned ne = __popc(nz);

        // warp inclusive scan of ne
        unsigned off = ne;
        #pragma unroll
        for (int o = 1; o < 32; o <<= 1) {
            unsigned v = __shfl_up_sync(0xffffffffu, off, o);
            if (lane >= o) off += v;
        }
        unsigned tot = __shfl_sync(0xffffffffu, off, 31);
        unsigned exc = off - ne;
        unsigned base = 0;
        if (lane == 31) base = atomicAdd(&s_n, tot);
        base = __shfl_sync(0xffffffffu, base, 31);

        unsigned gw8 = ((row0 + r) * WPR + wc) * 8;
        unsigned pos = base + exc;
        #pragma unroll
        for (int k = 0; k < 8; k++) if (nz & (1u << k)) {
            unsigned nib = (m >> (k * 4)) & 0xFu;
            stage[pos++] = (nib << 16) | (gw8 + k);
        }

        #pragma unroll
        for (int o = 16; o; o >>= 1) cnt += __shfl_down_sync(0xffffffffu, cnt, o);
        if (lane == 0) wcnt[warp] = cnt;
    }
    __syncthreads();

    // ---- phase D: histogram from dense staged worklist + write segment out ----
    const unsigned n = s_n;
    const float4* img4 = (const float4*)images + (size_t)b * G4PB;
    const float SCALEF = 256.0f / 255.0f;
    for (unsigned i = tid; i < n; i += 256) {
        unsigned e = stage[i];
        g_wl[b][strip][i] = e;
        unsigned g = e & 0xFFFFu, nib = e >> 16;
        float4 v = __ldg(img4 + g);
        float vs[4] = {v.x, v.y, v.z, v.w};
        #pragma unroll
        for (int k = 0; k < 4; k++) if (nib & (1u << k)) {
            float v255 = vs[k] * 255.0f;
            int idx = (int)floorf(v255 * SCALEF);
            idx = idx < 0 ? 0 : (idx > 255 ? 255 : idx);
            atomicAdd(&sh_hist[idx], 1u);
        }
    }
    __syncthreads();

    g_histp[b][strip][tid] = sh_hist[tid];
    if (tid == 0) {
        unsigned t = 0;
        #pragma unroll
        for (int i = 0; i < 8; i++) t += wcnt[i];
        g_cntp[b][strip] = t;
        g_wln[b][strip] = n;
    }

    // ---- election: last strip-block of this batch runs Otsu ----
    __threadfence();
    __syncthreads();
    if (tid == 0) s_rank = atomicInc(&g_done1[b], NSTR - 1);   // wraps to 0 -> replay safe
    __syncthreads();
    if (s_rank != NSTR - 1) return;
    __threadfence();

    // ---- Otsu for batch b (alias otsu arrays onto stage/lw/hwv shared) ----
    {
        float* h    = (float*)stage;            // 256
        float* a    = (float*)stage + 256;      // 256
        float* cmv  = (float*)stage + 512;      // 256
        float* term2 = (float*)stage + 768;     // 254
        unsigned char* w2pos = (unsigned char*)((float*)stage + 1024);  // 254 B
        float* sbest = (float*)lw;              // 256 (lw: 320 words)
        int*   sidx  = (int*)hwv;               // 256 (hwv: 320 words)
        __shared__ float s_total;

        unsigned hc = 0;
        #pragma unroll
        for (int s = 0; s < NSTR; s++) hc += __ldcg(&g_histp[b][s][tid]);
        if (tid == 0) {
            unsigned t = 0;
            #pragma unroll
            for (int s = 0; s < NSTR; s++) t += __ldcg(&g_cntp[b][s]);
            s_total = (float)t;
        }
        __syncthreads();
        h[tid] = (float)hc / s_total;
        __syncthreads();

        if (tid == 0) {                         // sequential cumsum == jnp order
            float c = 0.0f, c2 = 0.0f;
            for (int i = 0; i < 256; i++) {
                c  += h[i];              a[i]   = c;
                c2 += h[i] * (float)i;   cmv[i] = c2;
            }
        }
        __syncthreads();

        const float tm = cmv[255];
        const float s = 1e-8f;
        if (tid < NTHR) {
            float cb = a[tid], w2 = 1.0f - cb;
            float mean2 = (tm - cmv[tid]) / (w2 + s);
            float d2 = mean2 - tm;
            term2[tid] = w2 * (d2 * d2);
            w2pos[tid] = w2 > 0.0f;
        }
        __syncthreads();

        float best = -1.0f;
        int bflat = 0x7fffffff;
        if (tid < NTHR) {
            const int i = tid;
            float w0 = a[i], m0 = cmv[i];
            float mean0 = m0 / (w0 + s);
            float d0 = mean0 - tm;
            float term0 = w0 * (d0 * d0);
            bool p0 = w0 > 0.0f;
            for (int j = 0; j < NTHR; j++) {
                float w1 = a[j] - w0;
                float mean1 = (cmv[j] - m0) / (w1 + s);
                float d1 = mean1 - tm;
                float bv = term0 + w1 * (d1 * d1) + term2[j];
                bv = (p0 && w1 > 0.0f && w2pos[j]) ? bv : 0.0f;
                if (bv > best) { best = bv; bflat = i * NTHR + j; }
            }
        }
        sbest[tid] = best; sidx[tid] = bflat;
        __syncthreads();
        for (int st = 128; st; st >>= 1) {      // min-flat tie-break == jnp.argmax
            if (tid < st) {
                if (sbest[tid + st] > sbest[tid] ||
                    (sbest[tid + st] == sbest[tid] && sidx[tid + st] < sidx[tid])) {
                    sbest[tid] = sbest[tid + st];
                    sidx[tid]  = sidx[tid + st];
                }
            }
            __syncthreads();
        }
        if (tid == 0) {
            int am = sidx[0];
            g_t1[b] = (float)(am / NTHR + 1) / 255.0f;
            g_t2[b] = (float)(am % NTHR + 1) / 255.0f;
        }
    }
}

// ======== K2: masked squared-error over worklist + (last block) final scalar ========
__global__ __launch_bounds__(256) void lossKernel(const float* __restrict__ preds,
                                                  const float* __restrict__ images,
                                                  float* __restrict__ out) {
    const int b = blockIdx.y, strip = blockIdx.x;
    const int tid = threadIdx.x, lane = tid & 31, warp = tid >> 5;
    const float t1 = g_t1[b], t2 = g_t2[b];
    const unsigned n = g_wln[b][strip];
    const float4* img4 = (const float4*)images + (size_t)b * G4PB;
    const float4* prd4 = (const float4*)preds  + (size_t)b * G4PB;

    __shared__ float wsum[8];
    __shared__ unsigned s_rank;

    float acc = 0.0f;
    for (unsigned i = tid; i < n; i += 256) {
        unsigned e = g_wl[b][strip][i];
        unsigned g = e & 0xFFFFu, nib = e >> 16;
        float4 iv = __ldg(img4 + g);
        float4 pv = __ldcs(prd4 + g);
        float is[4] = {iv.x, iv.y, iv.z, iv.w};
        float ps[4] = {pv.x, pv.y, pv.z, pv.w};
        #pragma unroll
        for (int k = 0; k < 4; k++) if (nib & (1u << k)) {
            float ci = (is[k] >= t2) ? 1.0f : ((is[k] >= t1) ? 0.5f : 0.0f);
            float d = ci - ps[k];
            acc = fmaf(d, d, acc);
        }
    }
    #pragma unroll
    for (int o = 16; o; o >>= 1) acc += __shfl_down_sync(0xffffffffu, acc, o);
    if (lane == 0) wsum[warp] = acc;
    __syncthreads();
    if (tid == 0) {
        float v = 0.0f;
        #pragma unroll
        for (int i = 0; i < 8; i++) v += wsum[i];
        g_sqp[b][strip] = v;
    }

    // ---- election: very last block computes the final scalar ----
    __threadfence();
    __syncthreads();
    if (tid == 0) s_rank = atomicInc(&g_done2, NBLK - 1);      // wraps -> replay safe
    __syncthreads();
    if (s_rank != NBLK - 1) return;
    __threadfence();

    if (tid < 32) {
        int bb = tid;
        float sq = 0.0f; unsigned cnt = 0;
        #pragma unroll
        for (int s = 0; s < NSTR; s++) {
            sq  += __ldcg(&g_sqp[bb][s]);
            cnt += __ldcg(&g_cntp[bb][s]);
        }
        float sm = (float)cnt + 1e-8f;
        bool valid = sm > 1e-8f;
        float lp = valid ? (sq / sm) : 0.0f;
        int c = valid ? 1 : 0;
        #pragma unroll
        for (int o = 16; o; o >>= 1) {
            lp += __shfl_down_sync(0xffffffffu, lp, o);
            c  += __shfl_down_sync(0xffffffffu, c, o);
        }
        if (tid == 0) out[0] = (c > 0) ? (lp / (float)(c > 1 ? c : 1)) : 0.0f;
    }
}

// ---------------- launch ----------------
extern "C" void kernel_launch(void* const* d_in, const int* in_sizes, int n_in,
                              void* d_out, int out_size) {
    const float* preds  = (const float*)d_in[0];
    const float* labels = (const float*)d_in[1];
    const float* images = (const float*)d_in[2];
    float* out = (float*)d_out;
    (void)in_sizes; (void)n_in; (void)out_size;

    dim3 grid(NSTR, BATCH);                    // 32 x 32 = 1024 blocks
    fusedKernel<<<grid, 256>>>(labels, images);
    lossKernel<<<grid, 256>>>(preds, images, out);
}